// round 7
// baseline (speedup 1.0000x reference)
#include <cuda_runtime.h>
#include <cstdint>

// LorenzSDE ShARK — warp-private double-buffered cp.async pipelines, v7.
//   Geometry identical to R4 (best: 91.1us, DRAM 85.6%): TILE=128,
//   BLOCK=128, 30KB smem, grid 1024, 7 CTAs/SM. Change: each of the 4
//   warps owns a private 32-element sub-tile + private smem double buffer.
//   All CTA barriers -> __syncwarp. 28 independent pipelines/SM instead of
//   7 phase-locked ones -> smoother DRAM request injection.

#define BLOCK 128
#define TILE  128
#define NWARP 4
#define W4W   120     // float4 per warp per tensor: 32 elem * 15 f / 4
#define GRID  1024    // 32768 tiles / 1024 = 32 tiles per CTA, exact

__device__ __forceinline__ void cp16(void* sptr, const void* gptr) {
    uint32_t s = (uint32_t)__cvta_generic_to_shared(sptr);
    asm volatile("cp.async.cg.shared.global [%0], [%1], 16;"
                 :: "r"(s), "l"(gptr) : "memory");
}
#define CP_COMMIT() asm volatile("cp.async.commit_group;" ::: "memory")
#define CP_WAIT(N)  asm volatile("cp.async.wait_group %0;" :: "n"(N) : "memory")

__global__ __launch_bounds__(BLOCK) void lorenz_shark_kernel(
    const float* __restrict__ g_x,
    const float* __restrict__ g_dW,
    const float* __restrict__ g_dH,
    float* __restrict__ g_out,
    int n_tiles)
{
    // [buf][warp][data]  -> 2*4*120*16 = 15360 B each, 30 KB total
    __shared__ float4 s_w[2][NWARP][W4W];
    __shared__ float4 s_h[2][NWARP][W4W];

    const int lane = threadIdx.x & 31;
    const int wid  = threadIdx.x >> 5;

    const float DT  = 0.01f;
    const float CW  = 0.2f;                  // NOISE*sqrt(DT)
    const float CH  = 0.05773502691896258f;  // NOISE*sqrt(DT/12)
    const float SIG = 10.0f;
    const float RHO = 28.0f;
    const float BET = 8.0f / 3.0f;
    const float A56 = (5.0f / 6.0f) * DT;
    const float B56 = 5.0f / 6.0f;

    int tile = blockIdx.x;
    if (tile >= n_tiles) return;

    // warp's element base within a tile: tile*128 + wid*32
    auto prefetch_wh = [&](int buf, int t) {
        const long long eb = (long long)t * TILE + wid * 32;   // element base
        const float4* gw = reinterpret_cast<const float4*>(g_dW + eb * 15);
        const float4* gh = reinterpret_cast<const float4*>(g_dH + eb * 15);
        #pragma unroll
        for (int i = lane; i < W4W; i += 32) {
            cp16(&s_w[buf][wid][i], gw + i);
            cp16(&s_h[buf][wid][i], gh + i);
        }
    };

    // ---- prologue ----
    prefetch_wh(0, tile);
    CP_COMMIT();
    const float* xp = g_x + ((long long)tile * TILE + wid * 32 + lane) * 3;
    float xr0 = __ldcs(xp + 0), xr1 = __ldcs(xp + 1), xr2 = __ldcs(xp + 2);

    int buf = 0;
    for (; tile < n_tiles; tile += GRID) {
        const int next = tile + GRID;

        float nx0 = 0.f, nx1 = 0.f, nx2 = 0.f;
        if (next < n_tiles) {
            prefetch_wh(buf ^ 1, next);
            CP_COMMIT();
            const float* nxp = g_x + ((long long)next * TILE + wid * 32 + lane) * 3;
            nx0 = __ldcs(nxp + 0); nx1 = __ldcs(nxp + 1); nx2 = __ldcs(nxp + 2);
            CP_WAIT(1);          // current tile's group complete (per-thread)
        } else {
            CP_WAIT(0);
        }
        __syncwarp();            // lanes' cp.async data visible warp-wide

        const float* w = reinterpret_cast<const float*>(s_w[buf][wid]);
        const float* h = reinterpret_cast<const float*>(s_h[buf][wid]);

        float y0 = xr0, y1 = xr1, y2 = xr2;

        #pragma unroll
        for (int s = 0; s < 5; ++s) {
            const float w0 = w[lane * 15 + s * 3 + 0] * CW;
            const float w1 = w[lane * 15 + s * 3 + 1] * CW;
            const float w2 = w[lane * 15 + s * 3 + 2] * CW;
            const float h0 = h[lane * 15 + s * 3 + 0] * CH;
            const float h1 = h[lane * 15 + s * 3 + 1] * CH;
            const float h2 = h[lane * 15 + s * 3 + 2] * CH;

            const float z10 = y0 + h0;
            const float z11 = y1 + h1;
            const float z12 = y2 + h2;
            const float f10 = SIG * (z11 - z10);
            const float f11 = z10 * (RHO - z12) - z11;
            const float f12 = z10 * z11 - BET * z12;
            const float z20 = y0 + A56 * f10 + B56 * w0 + h0;
            const float z21 = y1 + A56 * f11 + B56 * w1 + h1;
            const float z22 = y2 + A56 * f12 + B56 * w2 + h2;
            const float f20 = SIG * (z21 - z20);
            const float f21 = z20 * (RHO - z22) - z21;
            const float f22 = z20 * z21 - BET * z22;
            y0 = y0 + DT * (0.4f * f10 + 0.6f * f20) + w0;
            y1 = y1 + DT * (0.4f * f11 + 0.6f * f21) + w1;
            y2 = y2 + DT * (0.4f * f12 + 0.6f * f22) + w2;
        }

        // streaming store; warp covers contiguous 384B -> sectors fully written
        float* op = g_out + ((long long)tile * TILE + wid * 32 + lane) * 3;
        __stcs(op + 0, y0);
        __stcs(op + 1, y1);
        __stcs(op + 2, y2);

        // all lanes' reads of s_*[buf][wid] done before next iteration's
        // prefetch (by any lane of this warp) overwrites that buffer.
        __syncwarp();

        xr0 = nx0; xr1 = nx1; xr2 = nx2;
        buf ^= 1;
    }
}

extern "C" void kernel_launch(void* const* d_in, const int* in_sizes, int n_in,
                              void* d_out, int out_size) {
    const float* x  = (const float*)d_in[0];
    const float* dW = (const float*)d_in[1];
    const float* dH = (const float*)d_in[2];
    float* out = (float*)d_out;

    const int n = in_sizes[0] / 3;        // 4194304, multiple of TILE
    const int n_tiles = n / TILE;         // 32768
    int grid = GRID;                      // exact 32 tiles/CTA
    if (grid > n_tiles) grid = n_tiles;
    lorenz_shark_kernel<<<grid, BLOCK>>>(x, dW, dH, out, n_tiles);
}

// round 8
// speedup vs baseline: 1.0222x; 1.0222x over previous
#include <cuda_runtime.h>
#include <cstdint>

// LorenzSDE ShARK — persistent double-buffered cp.async pipeline (FINAL).
//   This is the R4 kernel, re-banked after three falsified structural
//   perturbations (R5 deeper ring: 97.0us; R6 half-tiles: 92.2us; R7
//   warp-private pipelines: 92.7us) all regressed vs this version (91.1us,
//   DRAM 85.6%, 6.78 TB/s). Measured traffic equals the 604MB theoretical
//   minimum, so this sits at the practical HBM-controller floor for the
//   11:1 read/write mix.
//
//   Structure:
//   - persistent grid 1024 CTAs (7/SM), each exactly 32 tiles (no ragged tail)
//   - TILE=128: dW/dH (11/12 of traffic) double-buffered in smem via
//     cp.async.cg (L1-bypass), next tile streaming while current computes
//   - x prefetched one tile ahead into registers (streaming loads),
//     output stored directly from registers (streaming stores, full sectors)

#define BLOCK 128
#define TILE  128
#define W4    (TILE * 15 / 4)   // 480 float4 per tile for dW (and dH)
#define GRID  1024              // 32768 / 1024 = 32 tiles per CTA, exact

__device__ __forceinline__ void cp16(void* sptr, const void* gptr) {
    uint32_t s = (uint32_t)__cvta_generic_to_shared(sptr);
    asm volatile("cp.async.cg.shared.global [%0], [%1], 16;"
                 :: "r"(s), "l"(gptr) : "memory");
}
#define CP_COMMIT() asm volatile("cp.async.commit_group;" ::: "memory")
#define CP_WAIT(N)  asm volatile("cp.async.wait_group %0;" :: "n"(N) : "memory")

__global__ __launch_bounds__(BLOCK) void lorenz_shark_kernel(
    const float* __restrict__ g_x,
    const float* __restrict__ g_dW,
    const float* __restrict__ g_dH,
    float* __restrict__ g_out,
    int n_tiles)
{
    __shared__ float4 s_w[2][W4];   // 2 x 7.5 KB
    __shared__ float4 s_h[2][W4];   // 2 x 7.5 KB -> 30 KB total, 7 CTAs/SM

    const int tid = threadIdx.x;

    const float DT  = 0.01f;
    const float CW  = 0.2f;                  // NOISE*sqrt(DT)
    const float CH  = 0.05773502691896258f;  // NOISE*sqrt(DT/12)
    const float SIG = 10.0f;
    const float RHO = 28.0f;
    const float BET = 8.0f / 3.0f;
    const float A56 = (5.0f / 6.0f) * DT;
    const float B56 = 5.0f / 6.0f;

    int tile = blockIdx.x;
    if (tile >= n_tiles) return;

    auto prefetch_wh = [&](int buf, int t) {
        const float4* gw = reinterpret_cast<const float4*>(g_dW + (long long)t * TILE * 15);
        const float4* gh = reinterpret_cast<const float4*>(g_dH + (long long)t * TILE * 15);
        #pragma unroll
        for (int i = tid; i < W4; i += BLOCK) {
            cp16(&s_w[buf][i], gw + i);
            cp16(&s_h[buf][i], gh + i);
        }
    };

    // ---- prologue: prefetch tile 0 (smem) + x(tile 0) (regs, streaming) ----
    prefetch_wh(0, tile);
    CP_COMMIT();
    const float* xp = g_x + (long long)tile * TILE * 3 + tid * 3;
    float xr0 = __ldcs(xp + 0), xr1 = __ldcs(xp + 1), xr2 = __ldcs(xp + 2);

    int buf = 0;
    for (; tile < n_tiles; tile += GRID) {
        const int next = tile + GRID;

        float nx0 = 0.f, nx1 = 0.f, nx2 = 0.f;
        if (next < n_tiles) {
            prefetch_wh(buf ^ 1, next);
            CP_COMMIT();
            const float* nxp = g_x + (long long)next * TILE * 3 + tid * 3;
            nx0 = __ldcs(nxp + 0); nx1 = __ldcs(nxp + 1); nx2 = __ldcs(nxp + 2);
            CP_WAIT(1);          // current tile's group complete
        } else {
            CP_WAIT(0);
        }
        __syncthreads();         // all threads' cp.async data visible

        const float* w = reinterpret_cast<const float*>(s_w[buf]);
        const float* h = reinterpret_cast<const float*>(s_h[buf]);

        float y0 = xr0, y1 = xr1, y2 = xr2;

        #pragma unroll
        for (int s = 0; s < 5; ++s) {
            const float w0 = w[tid * 15 + s * 3 + 0] * CW;
            const float w1 = w[tid * 15 + s * 3 + 1] * CW;
            const float w2 = w[tid * 15 + s * 3 + 2] * CW;
            const float h0 = h[tid * 15 + s * 3 + 0] * CH;
            const float h1 = h[tid * 15 + s * 3 + 1] * CH;
            const float h2 = h[tid * 15 + s * 3 + 2] * CH;

            const float z10 = y0 + h0;
            const float z11 = y1 + h1;
            const float z12 = y2 + h2;
            const float f10 = SIG * (z11 - z10);
            const float f11 = z10 * (RHO - z12) - z11;
            const float f12 = z10 * z11 - BET * z12;
            const float z20 = y0 + A56 * f10 + B56 * w0 + h0;
            const float z21 = y1 + A56 * f11 + B56 * w1 + h1;
            const float z22 = y2 + A56 * f12 + B56 * w2 + h2;
            const float f20 = SIG * (z21 - z20);
            const float f21 = z20 * (RHO - z22) - z21;
            const float f22 = z20 * z21 - BET * z22;
            y0 = y0 + DT * (0.4f * f10 + 0.6f * f20) + w0;
            y1 = y1 + DT * (0.4f * f11 + 0.6f * f21) + w1;
            y2 = y2 + DT * (0.4f * f12 + 0.6f * f22) + w2;
        }

        // direct streaming store (stride-3 scalar; warp covers contiguous
        // 384B so sectors are fully written -> no write-allocate reads)
        float* op = g_out + (long long)tile * TILE * 3 + tid * 3;
        __stcs(op + 0, y0);
        __stcs(op + 1, y1);
        __stcs(op + 2, y2);

        // separates this tile's smem reads from the next prefetch that
        // overwrites this buffer.
        __syncthreads();

        xr0 = nx0; xr1 = nx1; xr2 = nx2;
        buf ^= 1;
    }
}

extern "C" void kernel_launch(void* const* d_in, const int* in_sizes, int n_in,
                              void* d_out, int out_size) {
    const float* x  = (const float*)d_in[0];
    const float* dW = (const float*)d_in[1];
    const float* dH = (const float*)d_in[2];
    float* out = (float*)d_out;

    const int n = in_sizes[0] / 3;        // 4194304, multiple of TILE
    const int n_tiles = n / TILE;         // 32768
    int grid = GRID;                      // exact 32 tiles/CTA, single wave
    if (grid > n_tiles) grid = n_tiles;
    lorenz_shark_kernel<<<grid, BLOCK>>>(x, dW, dH, out, n_tiles);
}